// round 4
// baseline (speedup 1.0000x reference)
#include <cuda_runtime.h>
#include <math.h>

// fl(sqrt(2)) and fl(1.5/sqrt(2)) exactly as numpy computes them (double -> float32).
// KODD = fp32 product, used for the sqrt2 / odd-exponent branch:
//   reference: pow(sqrt2f, e) * APPROX  ==  2^((e-1)/2) * (sqrt2f * APPROXf)  (within ~2 ulp)
__device__ __forceinline__ float quant_one(float x, float z, float c, float L,
                                           float s, float ls, float low)
{
    const float SQRT2F  = (float)1.4142135623730951;
    const float APPROXF = (float)1.0606601717798212;   // 1.5/sqrt(2) rounded to fp32
    const float KODD    = SQRT2F * APPROXF;            // constant-folded fp32 product

    float ax = fabsf(x);
    // log2(|x|/s) = log2|x| - log2(s); reference's +1e-32 only matters at x==0,
    // where log2f(0) = -inf drives the same zero-flag path (sign(0)=0 anyway).
    float xl = log2f(ax) - ls;
    bool  rt2 = (c != 2.0f);                 // code_map is exactly 2.0f or sqrt2f
    if (rt2) xl += xl;                       // log base sqrt2 = 2 * log2
    float xi = rintf(xl);                    // round-half-even == jnp.round
    float c1 = fmaxf(xi - z, low);           // clamp(min=lower)
    float xc = fminf(c1 - L, -1.0f);         // clamp(max=-1)
    float e  = xc + L + z;                   // integer in [-7, 9] on all live paths

    int ei = (int)e;                         // exact for integral e; dead paths don't care
    float q;
    if (rt2) {
        int h = ei >> 1;                     // floor(e/2), arithmetic shift
        q = __int_as_float((h + 127) << 23); // 2^h  (exact)
        if (ei & 1) q *= KODD;               // odd e: 2^h * sqrt2 * approx_factor
    } else {
        q = __int_as_float((ei + 127) << 23);// 2^e  (exact, matches pow(2,e))
    }
    if (c1 <= low) q = 0.0f;                 // underflow -> exact 0
    return q * copysignf(s, x);              // q * sign(x) * scale (x==0 -> q==0)
}

// Single fused kernel, smem row-param staging. A 256-float4 block spans at most
// 2 rows (2752 float4/row); 2 threads compute (s, log2 s, lower) into smem, the
// rest select by one compare. Memory shape identical to R1/R3: 4 front-batched
// LDG.128 + 1 STG.128 per thread, default cache ops.
__global__ void __launch_bounds__(256)
quant_kernel(const float4* __restrict__ X,
             const float4* __restrict__ Z,
             const float4* __restrict__ C,
             const float4* __restrict__ L,
             const float*  __restrict__ scale,
             const float*  __restrict__ asym,
             float4* __restrict__ O,
             int nvec)
{
    const int COLSV = 11008 / 4;             // 2752 float4 per row
    __shared__ float4 rp[2];                 // {s, log2 s, lower, _} for the 2 rows

    int base = blockIdx.x * 256;
    int idx  = base + threadIdx.x;
    int r0   = base / COLSV;                 // compile-time divisor -> mulhi

    if (threadIdx.x < 2) {
        // rows covered by this block: r0 and min(r0+1, last); clamp keeps loads in-bounds
        int rlast = (base + 255) / COLSV;
        int r = (threadIdx.x == 0) ? r0 : rlast;
        float s = scale[r];
        float a = asym[r];
        rp[threadIdx.x] = make_float4(s, log2f(s), fmaf(a, -0.5f, -1.0f), 0.0f);
    }

    // Issue wide loads before the barrier (independent of smem).
    bool live = idx < nvec;
    float4 x, z, c, l;
    if (live) { x = X[idx]; z = Z[idx]; c = C[idx]; l = L[idx]; }

    __syncthreads();

    if (!live) return;
    int bound = (r0 + 1) * COLSV;            // first index of the next row
    float4 p  = rp[idx >= bound ? 1 : 0];

    float4 o;
    o.x = quant_one(x.x, z.x, c.x, l.x, p.x, p.y, p.z);
    o.y = quant_one(x.y, z.y, c.y, l.y, p.x, p.y, p.z);
    o.z = quant_one(x.z, z.z, c.z, l.z, p.x, p.y, p.z);
    o.w = quant_one(x.w, z.w, c.w, l.w, p.x, p.y, p.z);
    O[idx] = o;
}

extern "C" void kernel_launch(void* const* d_in, const int* in_sizes, int n_in,
                              void* d_out, int out_size)
{
    // metadata order: x, scale, zero, code_map, level_map, asym_map
    const float* x     = (const float*)d_in[0];
    const float* scale = (const float*)d_in[1];
    const float* zero  = (const float*)d_in[2];
    const float* code  = (const float*)d_in[3];
    const float* level = (const float*)d_in[4];
    const float* asym  = (const float*)d_in[5];

    int nvec   = out_size / 4;               // 11,272,192 (divides 256 exactly)
    int blocks = (nvec + 255) / 256;

    quant_kernel<<<blocks, 256>>>((const float4*)x, (const float4*)zero,
                                  (const float4*)code, (const float4*)level,
                                  scale, asym, (float4*)d_out, nvec);
}

// round 5
// speedup vs baseline: 1.0346x; 1.0346x over previous
#include <cuda_runtime.h>
#include <math.h>

// fl(sqrt(2)) and fl(1.5/sqrt(2)) exactly as numpy computes them (double -> float32).
// KODD = fp32 product, used for the sqrt2 / odd-exponent branch:
//   reference: pow(sqrt2f, e) * APPROX  ==  2^((e-1)/2) * (sqrt2f * APPROXf)  (within ~2 ulp)
__device__ __forceinline__ float quant_one(float x, float z, float c, float L,
                                           float s, float ls, float low)
{
    const float SQRT2F  = (float)1.4142135623730951;
    const float APPROXF = (float)1.0606601717798212;   // 1.5/sqrt(2) rounded to fp32
    const float KODD    = SQRT2F * APPROXF;            // constant-folded fp32 product

    float ax = fabsf(x);
    // log2(|x|/s) = log2|x| - log2(s); reference's +1e-32 only matters at x==0,
    // where log2f(0) = -inf drives the same zero-flag path (sign(0)=0 anyway).
    float xl = log2f(ax) - ls;
    bool  rt2 = (c != 2.0f);                 // code_map is exactly 2.0f or sqrt2f
    if (rt2) xl += xl;                       // log base sqrt2 = 2 * log2
    float xi = rintf(xl);                    // round-half-even == jnp.round
    float c1 = fmaxf(xi - z, low);           // clamp(min=lower)
    float xc = fminf(c1 - L, -1.0f);         // clamp(max=-1)
    float e  = xc + L + z;                   // integer in [-7, 9] on all live paths

    int ei = (int)e;                         // exact for integral e; dead paths don't care
    float q;
    if (rt2) {
        int h = ei >> 1;                     // floor(e/2), arithmetic shift
        q = __int_as_float((h + 127) << 23); // 2^h  (exact)
        if (ei & 1) q *= KODD;               // odd e: 2^h * sqrt2 * approx_factor
    } else {
        q = __int_as_float((ei + 127) << 23);// 2^e  (exact, matches pow(2,e))
    }
    if (c1 <= low) q = 0.0f;                 // underflow -> exact 0
    return q * copysignf(s, x);              // q * sign(x) * scale (x==0 -> q==0)
}

// R3 shape (proven fastest): single kernel, 1 float4/thread, 4 front-batched
// LDG.128 with default cache ops, warp-uniform row params (32 | 2752 so a warp
// never crosses a row -> scale/asym loads coalesce to one request per warp).
// Only change vs R3: evict-first streaming store for the zero-reuse output.
__global__ void __launch_bounds__(256)
quant_kernel(const float4* __restrict__ X,
             const float4* __restrict__ Z,
             const float4* __restrict__ C,
             const float4* __restrict__ L,
             const float*  __restrict__ scale,
             const float*  __restrict__ asym,
             float4* __restrict__ O,
             int nvec)
{
    const int COLSV = 11008 / 4;             // 2752 float4 per row (compile-time divisor)
    int idx = blockIdx.x * blockDim.x + threadIdx.x;
    if (idx >= nvec) return;
    int row = idx / COLSV;                   // warp-uniform

    // Front-batch the 4 wide loads (MLP_p1=4) + 2 broadcast scalars.
    float4 x = X[idx];
    float4 z = Z[idx];
    float4 c = C[idx];
    float4 l = L[idx];
    float  s = __ldg(scale + row);
    float  a = __ldg(asym  + row);

    float ls  = log2f(s);
    float low = fmaf(a, -0.5f, -1.0f);       // -1 - asym/2

    float4 o;
    o.x = quant_one(x.x, z.x, c.x, l.x, s, ls, low);
    o.y = quant_one(x.y, z.y, c.y, l.y, s, ls, low);
    o.z = quant_one(x.z, z.z, c.z, l.z, s, ls, low);
    o.w = quant_one(x.w, z.w, c.w, l.w, s, ls, low);
    __stcs(O + idx, o);                      // streaming store: zero reuse, evict-first
}

extern "C" void kernel_launch(void* const* d_in, const int* in_sizes, int n_in,
                              void* d_out, int out_size)
{
    // metadata order: x, scale, zero, code_map, level_map, asym_map
    const float* x     = (const float*)d_in[0];
    const float* scale = (const float*)d_in[1];
    const float* zero  = (const float*)d_in[2];
    const float* code  = (const float*)d_in[3];
    const float* level = (const float*)d_in[4];
    const float* asym  = (const float*)d_in[5];

    int nvec   = out_size / 4;               // total elems / 4 (COLS divisible by 4)
    int blocks = (nvec + 255) / 256;

    quant_kernel<<<blocks, 256>>>((const float4*)x, (const float4*)zero,
                                  (const float4*)code, (const float4*)level,
                                  scale, asym, (float4*)d_out, nvec);
}

// round 6
// speedup vs baseline: 1.0359x; 1.0012x over previous
#include <cuda_runtime.h>
#include <math.h>

// fl(sqrt(2)) and fl(1.5/sqrt(2)) exactly as numpy computes them (double -> float32).
// KODD = fp32 product, used for the sqrt2 / odd-exponent branch:
//   reference: pow(sqrt2f, e) * APPROX  ==  2^((e-1)/2) * (sqrt2f * APPROXf)  (within ~2 ulp)
__device__ __forceinline__ float quant_one(float x, float z, float c, float L,
                                           float s, float ls, float low)
{
    const float SQRT2F  = (float)1.4142135623730951;
    const float APPROXF = (float)1.0606601717798212;   // 1.5/sqrt(2) rounded to fp32
    const float KODD    = SQRT2F * APPROXF;            // constant-folded fp32 product

    float ax = fabsf(x);
    // log2(|x|/s) = log2|x| - log2(s); reference's +1e-32 only matters at x==0,
    // where log2f(0) = -inf drives the same zero-flag path (sign(0)=0 anyway).
    float xl = log2f(ax) - ls;
    bool  rt2 = (c != 2.0f);                 // code_map is exactly 2.0f or sqrt2f
    if (rt2) xl += xl;                       // log base sqrt2 = 2 * log2
    float xi = rintf(xl);                    // round-half-even == jnp.round
    float c1 = fmaxf(xi - z, low);           // clamp(min=lower)
    float xc = fminf(c1 - L, -1.0f);         // clamp(max=-1)
    float e  = xc + L + z;                   // integer in [-7, 9] on all live paths

    int ei = (int)e;                         // exact for integral e; dead paths don't care
    float q;
    if (rt2) {
        int h = ei >> 1;                     // floor(e/2), arithmetic shift
        q = __int_as_float((h + 127) << 23); // 2^h  (exact)
        if (ei & 1) q *= KODD;               // odd e: 2^h * sqrt2 * approx_factor
    } else {
        q = __int_as_float((ei + 127) << 23);// 2^e  (exact, matches pow(2,e))
    }
    if (c1 <= low) q = 0.0f;                 // underflow -> exact 0
    return q * copysignf(s, x);              // q * sign(x) * scale (x==0 -> q==0)
}

// Proven shape (R3): single kernel, 1 float4/thread, 4 front-batched LDG.128,
// warp-uniform row params. This round's single variable: evict-first streaming
// on BOTH the zero-reuse loads (__ldcs) and the store (__stcs).
__global__ void __launch_bounds__(256)
quant_kernel(const float4* __restrict__ X,
             const float4* __restrict__ Z,
             const float4* __restrict__ C,
             const float4* __restrict__ L,
             const float*  __restrict__ scale,
             const float*  __restrict__ asym,
             float4* __restrict__ O,
             int nvec)
{
    const int COLSV = 11008 / 4;             // 2752 float4 per row (compile-time divisor)
    int idx = blockIdx.x * blockDim.x + threadIdx.x;
    if (idx >= nvec) return;
    int row = idx / COLSV;                   // warp-uniform (32 | 2752)

    // Front-batch the 4 wide streaming loads (MLP_p1=4) + 2 broadcast scalars.
    float4 x = __ldcs(X + idx);
    float4 z = __ldcs(Z + idx);
    float4 c = __ldcs(C + idx);
    float4 l = __ldcs(L + idx);
    float  s = __ldg(scale + row);           // reused across row -> keep cached
    float  a = __ldg(asym  + row);

    float ls  = log2f(s);
    float low = fmaf(a, -0.5f, -1.0f);       // -1 - asym/2

    float4 o;
    o.x = quant_one(x.x, z.x, c.x, l.x, s, ls, low);
    o.y = quant_one(x.y, z.y, c.y, l.y, s, ls, low);
    o.z = quant_one(x.z, z.z, c.z, l.z, s, ls, low);
    o.w = quant_one(x.w, z.w, c.w, l.w, s, ls, low);
    __stcs(O + idx, o);                      // streaming store: zero reuse
}

extern "C" void kernel_launch(void* const* d_in, const int* in_sizes, int n_in,
                              void* d_out, int out_size)
{
    // metadata order: x, scale, zero, code_map, level_map, asym_map
    const float* x     = (const float*)d_in[0];
    const float* scale = (const float*)d_in[1];
    const float* zero  = (const float*)d_in[2];
    const float* code  = (const float*)d_in[3];
    const float* level = (const float*)d_in[4];
    const float* asym  = (const float*)d_in[5];

    int nvec   = out_size / 4;               // total elems / 4 (COLS divisible by 4)
    int blocks = (nvec + 255) / 256;

    quant_kernel<<<blocks, 256>>>((const float4*)x, (const float4*)zero,
                                  (const float4*)code, (const float4*)level,
                                  scale, asym, (float4*)d_out, nvec);
}